// round 8
// baseline (speedup 1.0000x reference)
#include <cuda_runtime.h>

// ---------------- problem constants ----------------
#define NB   64
#define DIN  768
#define HD   256
#define H2   512
#define NC   24
#define WOUT 512

// ---------------- scratch ----------------
__device__ float g_hid[NB * H2];
__device__ float g_shared_t[HD * NB];            // [c][b]
__device__ float g_rb[24 * HD];                  // rank bias: remb@W1bot + b1
__device__ float g_hdn[24 * HD * NB];            // [r][k][b]
__device__ float g_rf_t[24 * HD * NB];           // [r][h][b]
__device__ float g_hdn3[48 * HD * NB];           // [u][k][b]
__device__ float g_cp[4 * NB * 16 * NC];
__device__ float g_u[NB * 16 * WOUT];
__device__ float g_v[NB * 16 * WOUT];
__device__ float g_dx[NB * WOUT];
__device__ float g_dy[NB * WOUT];

// ---------------- helpers ----------------
typedef unsigned long long ull;

__device__ __forceinline__ ull pk2(float x, float y) {
    ull r; asm("mov.b64 %0, {%1,%2};" : "=l"(r) : "f"(x), "f"(y)); return r;
}
__device__ __forceinline__ void fma2(ull& d, ull a, ull b) {
    asm("fma.rn.f32x2 %0, %1, %2, %0;" : "+l"(d) : "l"(a), "l"(b));
}
__device__ __forceinline__ ull add2(ull a, ull b) {
    ull r; asm("add.rn.f32x2 %0, %1, %2;" : "=l"(r) : "l"(a), "l"(b)); return r;
}
__device__ __forceinline__ float2 up2(ull a) {
    float2 r; asm("mov.b64 {%0,%1}, %2;" : "=f"(r.x), "=f"(r.y) : "l"(a)); return r;
}
__device__ __forceinline__ float lk(float x) { return x >= 0.f ? x : 0.2f * x; }

__device__ __forceinline__ void cpa16(float* sdst, const float* gsrc) {
    unsigned sa = (unsigned)__cvta_generic_to_shared(sdst);
    asm volatile("cp.async.cg.shared.global [%0], [%1], 16;" :: "r"(sa), "l"(gsrc) : "memory");
}
#define CPA_COMMIT() asm volatile("cp.async.commit_group;" ::: "memory")

__device__ __forceinline__ void hcoef(int w, int& seg,
                                      float& h00, float& h10, float& h01, float& h11) {
    const float step = 0.998f / 511.f;
    float t  = 0.001f + (float)w * step;
    float ts = t * 23.f;
    int s = (int)floorf(ts);
    s = s < 0 ? 0 : (s > 22 ? 22 : s);
    float tau = ts - (float)s;
    tau = fminf(fmaxf(tau, 0.f), 0.9999f);
    float t2 = tau * tau, t3 = t2 * tau;
    h00 = 2.f * t3 - 3.f * t2 + 1.f;
    h10 = t3 - 2.f * t2 + tau;
    h01 = -2.f * t3 + 3.f * t2;
    h11 = t3 - t2;
    seg = s;
}
__device__ __forceinline__ float hermev(const float* cp, int s,
                                        float h00, float h10, float h01, float h11) {
    const float inv = 0.5f / 23.f;
    float pk  = cp[s];
    float pk1 = cp[s + 1];
    int jm = s - 1; if (jm < 0) jm = 0;
    float mk = (cp[s + 1] - cp[jm]) * inv;
    int j2 = s + 2; if (j2 > 23) j2 = 23;
    float mk1 = (cp[j2] - cp[s]) * inv;
    return h00 * pk + h10 * mk + h01 * pk1 + h11 * mk1;
}

// ======== GEMM v2 body: 64 cols x 16 batch, K=256 ========
// 256 threads: duo = tid&31 (2 adjacent cols), bg = tid>>5 (2 batches).
// xs[256][32]: batch-DUPLICATED activations (value at 2b and 2b+1).
// ws[2][32*64]: 2-stage weight double buffer (32 rows x 64 cols per stage).
// wsrc: gmem weights, row stride HD, pre-offset to block's 64-col slice.
// acc[4]: col-pair accumulators, even/odd k split. Result:
//   o0 = acc0+acc2 = (out[c0][b0], out[c1][b0]); o1 = acc1+acc3 = (.. b1)
__device__ __forceinline__ void gemm_body(const float* __restrict__ wsrc,
                                          const float* xs, float* ws,
                                          ull* acc, int tid) {
    int duo = tid & 31, bg = tid >> 5;

    // prologue: stage chunk 0
    {
        #pragma unroll
        for (int j = 0; j < 2; j++) {
            int t = tid + j * 256;
            int row = t >> 4, seg = t & 15;
            cpa16(ws + row * 64 + seg * 4, wsrc + row * HD + seg * 4);
        }
        CPA_COMMIT();
    }

    #pragma unroll 1
    for (int c = 0; c < 8; c++) {
        if (c < 7) {
            const float* gs = wsrc + (c + 1) * 32 * HD;
            float* wdst = ws + ((c + 1) & 1) * 2048;
            #pragma unroll
            for (int j = 0; j < 2; j++) {
                int t = tid + j * 256;
                int row = t >> 4, seg = t & 15;
                cpa16(wdst + row * 64 + seg * 4, gs + row * HD + seg * 4);
            }
            CPA_COMMIT();
            asm volatile("cp.async.wait_group 1;" ::: "memory");
        } else {
            asm volatile("cp.async.wait_group 0;" ::: "memory");
        }
        __syncthreads();
        const float* wst = ws + (c & 1) * 2048;
        const float* xc  = xs + c * 32 * 32 + bg * 4;
        #pragma unroll
        for (int kk = 0; kk < 32; kk++) {
            ull w01 = *(const ull*)(wst + kk * 64 + duo * 2);
            ulonglong2 xp = *(const ulonglong2*)(xc + kk * 32);
            if (kk & 1) { fma2(acc[2], w01, xp.x); fma2(acc[3], w01, xp.y); }
            else        { fma2(acc[0], w01, xp.x); fma2(acc[1], w01, xp.y); }
        }
        __syncthreads();
    }
}

// stage duplicated x[256][32] from global [256][NB] slab at batch offset b0 (16 batches)
__device__ __forceinline__ void stage_x16(float* xs, const float* __restrict__ src,
                                          int b0, int tid) {
    #pragma unroll
    for (int j = 0; j < 16; j++) {
        int i = tid + j * 256;
        int d = i >> 4, b = i & 15;
        float v = src[d * NB + b0 + b];
        *(float2*)(xs + d * 32 + 2 * b) = make_float2(v, v);
    }
}

// ---------------- K1a ----------------
__global__ void __launch_bounds__(512) k1a(const float* __restrict__ hin,
                                           const float* __restrict__ w1,
                                           const float* __restrict__ b1) {
    __shared__ __align__(16) float sm[DIN * 12];
    int tid = threadIdx.x;
    int c = tid & 63, ks = tid >> 6;
    int hc = blockIdx.x, btile = blockIdx.y;
    int b0 = btile * 8;
    int hcol = hc * 64 + c;

    for (int i = tid; i < 8 * DIN; i += 512) {
        int bb = i / DIN, d = i - bb * DIN;
        sm[d * 12 + bb] = hin[(b0 + bb) * DIN + d];
    }
    __syncthreads();

    ull acc[4];
#pragma unroll
    for (int j = 0; j < 4; j++) acc[j] = 0ull;
    const float* w1p = w1 + hcol;
    int d0 = ks * 96;
#pragma unroll 4
    for (int dd = 0; dd < 96; dd++) {
        int d = d0 + dd;
        float w = w1p[d * H2];
        ull wp = pk2(w, w);
        const ulonglong2* xr = (const ulonglong2*)(sm + d * 12);
        ulonglong2 p0 = xr[0], p1 = xr[1];
        fma2(acc[0], wp, p0.x); fma2(acc[1], wp, p0.y);
        fma2(acc[2], wp, p1.x); fma2(acc[3], wp, p1.y);
    }
    __syncthreads();
    ull* part = (ull*)sm;
#pragma unroll
    for (int j = 0; j < 4; j++) part[tid * 4 + j] = acc[j];
    __syncthreads();
    if (tid < 256) {
        int cc = tid & 63, j = tid >> 6;
        ull s = part[cc * 4 + j];
#pragma unroll
        for (int k = 1; k < 8; k++) s = add2(s, part[(k * 64 + cc) * 4 + j]);
        int hco = hc * 64 + cc;
        float2 p = up2(s);
        float bias = b1[hco];
        g_hid[(b0 + 2 * j) * H2 + hco]     = lk(p.x + bias);
        g_hid[(b0 + 2 * j + 1) * H2 + hco] = lk(p.y + bias);
    }
}

// ---------------- K1b ----------------
__global__ void __launch_bounds__(512) k1b(const float* __restrict__ w2,
                                           const float* __restrict__ b2) {
    __shared__ __align__(16) float sm[H2 * 8];
    int tid = threadIdx.x;
    int c = tid & 63, ks = tid >> 6;
    int cc = blockIdx.x, btile = blockIdx.y;
    int b0 = btile * 4;
    int ccol = cc * 64 + c;

    for (int i = tid; i < 4 * H2; i += 512) {
        int bb = i >> 9, d = i & 511;
        sm[d * 8 + bb] = g_hid[(b0 + bb) * H2 + d];
    }
    __syncthreads();

    ull acc[2] = {0ull, 0ull};
    const float* wp2 = w2 + ccol;
    int d0 = ks * 64;
#pragma unroll 4
    for (int dd = 0; dd < 64; dd++) {
        int d = d0 + dd;
        float w = wp2[d * HD];
        ull wp = pk2(w, w);
        ulonglong2 p0 = *(const ulonglong2*)(sm + d * 8);
        fma2(acc[0], wp, p0.x); fma2(acc[1], wp, p0.y);
    }
    __syncthreads();
    ull* part = (ull*)sm;
    part[tid * 2 + 0] = acc[0];
    part[tid * 2 + 1] = acc[1];
    __syncthreads();
    if (tid < 128) {
        int c2 = tid & 63, j = tid >> 6;
        ull s = part[c2 * 2 + j];
#pragma unroll
        for (int k = 1; k < 8; k++) s = add2(s, part[(k * 64 + c2) * 2 + j]);
        int co = cc * 64 + c2;
        float2 p = up2(s);
        float bias = b2[co];
        g_shared_t[co * NB + b0 + 2 * j]     = p.x + bias;
        g_shared_t[co * NB + b0 + 2 * j + 1] = p.y + bias;
    }
}

// ---------------- KRB ----------------
__global__ void __launch_bounds__(1024) krb(const float* __restrict__ remb,
                                            const float* __restrict__ w1,
                                            const float* __restrict__ b1) {
    __shared__ float part[1024];
    int tid = threadIdx.x;
    int col = tid & 255, ks = tid >> 8;
    int r = blockIdx.x;
    const float* wp = w1 + (r * H2 + HD + ks * 64) * HD + col;
    const float* rp = remb + r * HD + ks * 64;
    float a = 0.f;
#pragma unroll 8
    for (int d = 0; d < 64; d++)
        a = fmaf(__ldg(rp + d), wp[d * HD], a);
    part[tid] = a;
    __syncthreads();
    if (ks == 0) {
        a += part[256 + col] + part[512 + col] + part[768 + col];
        g_rb[r * HD + col] = a + b1[r * HD + col];
    }
}

// ---------------- K2a: hdn = leaky(shared @ W1_top + rb) ----------------
// grid (4 ch, 4 bh, 24 r), block 256
__global__ void __launch_bounds__(256) k2a(const float* __restrict__ w1) {
    __shared__ __align__(16) float xs[HD * 32];   // 32 KB
    __shared__ __align__(16) float ws[2 * 2048];  // 16 KB
    int tid = threadIdx.x;
    int ch = blockIdx.x, bh = blockIdx.y, r = blockIdx.z;
    int b0 = bh * 16;
    const float* wsrc = w1 + (size_t)r * H2 * HD + ch * 64;

    int duo = tid & 31, bg = tid >> 5;
    int col0 = ch * 64 + duo * 2;
    float2 rb = *(const float2*)(g_rb + r * HD + col0);

    stage_x16(xs, g_shared_t, b0, tid);

    ull acc[4] = {0ull, 0ull, 0ull, 0ull};
    gemm_body(wsrc, xs, ws, acc, tid);

    ull o0 = add2(acc[0], acc[2]);   // (c0,c1) @ b0
    ull o1 = add2(acc[1], acc[3]);   // (c0,c1) @ b1
    float2 p0 = up2(o0), p1 = up2(o1);
    float* base = g_hdn + (size_t)(r * HD + col0) * NB + b0 + bg * 2;
    *(float2*)(base)      = make_float2(lk(p0.x + rb.x), lk(p1.x + rb.x));
    *(float2*)(base + NB) = make_float2(lk(p0.y + rb.y), lk(p1.y + rb.y));
}

// ---------------- K2b: rf = hdn @ W2 + b2 ----------------
__global__ void __launch_bounds__(256) k2b(const float* __restrict__ w2,
                                           const float* __restrict__ b2) {
    __shared__ __align__(16) float xs[HD * 32];
    __shared__ __align__(16) float ws[2 * 2048];
    int tid = threadIdx.x;
    int ch = blockIdx.x, bh = blockIdx.y, r = blockIdx.z;
    int b0 = bh * 16;
    const float* wsrc = w2 + (size_t)r * HD * HD + ch * 64;

    int duo = tid & 31, bg = tid >> 5;
    int col0 = ch * 64 + duo * 2;
    float2 bias = *(const float2*)(b2 + r * HD + col0);

    stage_x16(xs, g_hdn + (size_t)r * HD * NB, b0, tid);

    ull acc[4] = {0ull, 0ull, 0ull, 0ull};
    gemm_body(wsrc, xs, ws, acc, tid);

    ull o0 = add2(acc[0], acc[2]);
    ull o1 = add2(acc[1], acc[3]);
    float2 p0 = up2(o0), p1 = up2(o1);
    float* base = g_rf_t + (size_t)(r * HD + col0) * NB + b0 + bg * 2;
    *(float2*)(base)      = make_float2(p0.x + bias.x, p1.x + bias.x);
    *(float2*)(base + NB) = make_float2(p0.y + bias.y, p1.y + bias.y);
}

// ---------------- K3a: cp-gen layer1, 48 units ----------------
// grid (4 ch, 4 bh, 48 u), block 256
__global__ void __launch_bounds__(256) k3a(
        const float* __restrict__ mxw1, const float* __restrict__ mxb1,
        const float* __restrict__ myw1, const float* __restrict__ myb1,
        const float* __restrict__ axw1, const float* __restrict__ axb1,
        const float* __restrict__ ayw1, const float* __restrict__ ayb1) {
    __shared__ __align__(16) float xs[HD * 32];
    __shared__ __align__(16) float ws[2 * 2048];
    int tid = threadIdx.x;
    int ch = blockIdx.x, bh = blockIdx.y, u = blockIdx.z;
    int b0 = bh * 16;

    const float *w1, *b1;
    int r, src_r;
    if (u < 16)      { r = u;      src_r = u;      w1 = mxw1; b1 = mxb1; }
    else if (u < 32) { r = u - 16; src_r = r;      w1 = myw1; b1 = myb1; }
    else if (u < 40) { r = u - 32; src_r = 16 + r; w1 = axw1; b1 = axb1; }
    else             { r = u - 40; src_r = 16 + r; w1 = ayw1; b1 = ayb1; }
    const float* wsrc = w1 + (size_t)r * HD * HD + ch * 64;

    int duo = tid & 31, bg = tid >> 5;
    int col0 = ch * 64 + duo * 2;
    float2 bias = *(const float2*)(b1 + r * HD + col0);

    stage_x16(xs, g_rf_t + (size_t)src_r * HD * NB, b0, tid);

    ull acc[4] = {0ull, 0ull, 0ull, 0ull};
    gemm_body(wsrc, xs, ws, acc, tid);

    ull o0 = add2(acc[0], acc[2]);
    ull o1 = add2(acc[1], acc[3]);
    float2 p0 = up2(o0), p1 = up2(o1);
    float* base = g_hdn3 + (size_t)(u * HD + col0) * NB + b0 + bg * 2;
    *(float2*)(base)      = make_float2(lk(p0.x + bias.x), lk(p1.x + bias.x));
    *(float2*)(base + NB) = make_float2(lk(p0.y + bias.y), lk(p1.y + bias.y));
}

// ---------------- K3b ----------------
__global__ void __launch_bounds__(256) k3b(
        const float* __restrict__ mxw2, const float* __restrict__ mxb2,
        const float* __restrict__ myw2, const float* __restrict__ myb2,
        const float* __restrict__ axw2, const float* __restrict__ axb2,
        const float* __restrict__ ayw2, const float* __restrict__ ayb2) {
    __shared__ __align__(16) float wcol[HD * 4];
    int tid = threadIdx.x;
    int b = tid & 63, ci = tid >> 6;
    int u = blockIdx.x, cg = blockIdx.y;
    int c = cg * 4 + ci;

    const float *w2, *b2;
    int r, gen;
    if (u < 16)      { r = u;      gen = 0; w2 = mxw2; b2 = mxb2; }
    else if (u < 32) { r = u - 16; gen = 1; w2 = myw2; b2 = myb2; }
    else if (u < 40) { r = u - 32; gen = 2; w2 = axw2; b2 = axb2; }
    else             { r = u - 40; gen = 3; w2 = ayw2; b2 = ayb2; }
    w2 += r * HD * NC; b2 += r * NC;

    for (int i = tid; i < HD * 4; i += 256) {
        int k = i >> 2, cc = i & 3;
        wcol[i] = w2[k * NC + cg * 4 + cc];
    }
    __syncthreads();

    const float* hp = g_hdn3 + (size_t)(u * HD) * NB + b;
    float a0 = 0.f, a1 = 0.f, a2 = 0.f, a3 = 0.f;
#pragma unroll 8
    for (int k = 0; k < HD; k += 4) {
        a0 = fmaf(wcol[(k + 0) * 4 + ci], hp[(k + 0) * NB], a0);
        a1 = fmaf(wcol[(k + 1) * 4 + ci], hp[(k + 1) * NB], a1);
        a2 = fmaf(wcol[(k + 2) * 4 + ci], hp[(k + 2) * NB], a2);
        a3 = fmaf(wcol[(k + 3) * 4 + ci], hp[(k + 3) * NB], a3);
    }
    float a = (a0 + a1) + (a2 + a3) + b2[c];
    g_cp[((gen * NB + b) * 16 + r) * NC + c] = a;
}

// ---------------- K4 ----------------
__global__ void __launch_bounds__(128) k4(const float* __restrict__ mw,
                                          const float* __restrict__ axw,
                                          const float* __restrict__ ayw,
                                          const float* __restrict__ gb) {
    __shared__ __align__(16) float cps[8][24];
    __shared__ float wg[16];
    int tid = threadIdx.x, x = blockIdx.x;

    if (x < 2048) {
        int isv = x >> 10;
        int xx = x & 1023;
        int b = xx >> 4, r = xx & 15;
        const float* cp = g_cp + ((isv * NB + b) * 16 + r) * NC;
        if (tid < NC) cps[0][tid] = cp[tid];
        if (tid == 0) {
            if (isv) {
                float mx = mw[0];
                for (int i = 1; i < 16; i++) mx = fmaxf(mx, mw[i]);
                float s = 0.f, er = 0.f;
                for (int i = 0; i < 16; i++) { float e = expf(mw[i] - mx); s += e; if (i == r) er = e; }
                wg[0] = er / s;
            } else wg[0] = 1.f;
        }
        __syncthreads();
        float sc = wg[0];
        float o[4];
#pragma unroll
        for (int i = 0; i < 4; i++) {
            int w = tid * 4 + i;
            int seg; float h00, h10, h01, h11;
            hcoef(w, seg, h00, h10, h01, h11);
            o[i] = sc * hermev(cps[0], seg, h00, h10, h01, h11);
        }
        float* op = (isv ? g_v : g_u) + (b * 16 + r) * WOUT + tid * 4;
        *(float4*)op = make_float4(o[0], o[1], o[2], o[3]);
    } else {
        int isy = (x >= 2112);
        int b = x - (isy ? 2112 : 2048);
        int gen = 2 + isy;
        for (int i = tid; i < 8 * NC; i += 128) {
            int rr = i / NC, c = i - rr * NC;
            cps[rr][c] = g_cp[((gen * NB + b) * 16 + rr) * NC + c];
        }
        if (tid == 0) {
            const float* ww = isy ? ayw : axw;
            float mx = ww[0];
            for (int i = 1; i < 8; i++) mx = fmaxf(mx, ww[i]);
            float s = 0.f, e[8];
            for (int i = 0; i < 8; i++) { e[i] = expf(ww[i] - mx); s += e[i]; }
            for (int i = 0; i < 8; i++) wg[i] = e[i] / s;
        }
        __syncthreads();
        float base = isy ? gb[0] : 0.f;
        float o[4];
#pragma unroll
        for (int i = 0; i < 4; i++) {
            int w = tid * 4 + i;
            int seg; float h00, h10, h01, h11;
            hcoef(w, seg, h00, h10, h01, h11);
            float a = base;
#pragma unroll
            for (int rr = 0; rr < 8; rr++)
                a = fmaf(wg[rr], hermev(cps[rr], seg, h00, h10, h01, h11), a);
            o[i] = a;
        }
        float* op = (isy ? g_dy : g_dx) + b * WOUT + tid * 4;
        *(float4*)op = make_float4(o[0], o[1], o[2], o[3]);
    }
}

// ---------------- K5 ----------------
__global__ void __launch_bounds__(128) k5(float* __restrict__ out) {
    __shared__ __align__(16) float wv[32][36];
    __shared__ float dys[32];
    int tid = threadIdx.x;
    int ht = blockIdx.x, b = blockIdx.y;
    int h0 = ht * 32;

    for (int i = tid; i < 512; i += 128) {
        int r = i >> 5, hh = i & 31;
        float v = g_v[(b * 16 + r) * WOUT + h0 + hh];
        wv[hh][2 * r] = v;
        wv[hh][2 * r + 1] = v;
    }
    if (tid < 32) dys[tid] = g_dy[b * WOUT + h0 + tid];

    int w = tid * 4;
    ull ur2[32];
#pragma unroll
    for (int r = 0; r < 16; r++) {
        float4 t = *(const float4*)(g_u + (b * 16 + r) * WOUT + w);
        ur2[2 * r]     = pk2(t.x, t.y);
        ur2[2 * r + 1] = pk2(t.z, t.w);
    }
    float4 dx4 = *(const float4*)(g_dx + b * WOUT + w);
    ull dxp0 = pk2(dx4.x, dx4.y), dxp1 = pk2(dx4.z, dx4.w);
    __syncthreads();

    float* op = out + (size_t)b * (512 * 512) + (size_t)h0 * 512 + w;
#pragma unroll 2
    for (int hh = 0; hh < 32; hh++) {
        float dyv = dys[hh];
        ull dyp = pk2(dyv, dyv);
        ull a0 = add2(dxp0, dyp);
        ull a1 = add2(dxp1, dyp);
        const ulonglong2* row = (const ulonglong2*)&wv[hh][0];
#pragma unroll
        for (int i = 0; i < 8; i++) {
            ulonglong2 c = row[i];
            fma2(a0, c.x, ur2[4 * i]);
            fma2(a1, c.x, ur2[4 * i + 1]);
            fma2(a0, c.y, ur2[4 * i + 2]);
            fma2(a1, c.y, ur2[4 * i + 3]);
        }
        float2 lo = up2(a0), hi = up2(a1);
        *(float4*)(op + hh * 512) = make_float4(lo.x, lo.y, hi.x, hi.y);
    }
}

// ---------------- launch ----------------
extern "C" void kernel_launch(void* const* d_in, const int* in_sizes, int n_in,
                              void* d_out, int out_size) {
    const float* h_in   = (const float*)d_in[0];
    const float* remb   = (const float*)d_in[1];
    const float* st_w1  = (const float*)d_in[2];
    const float* st_b1  = (const float*)d_in[3];
    const float* st_w2  = (const float*)d_in[4];
    const float* st_b2  = (const float*)d_in[5];
    const float* rm_w1  = (const float*)d_in[6];
    const float* rm_b1  = (const float*)d_in[7];
    const float* rm_w2  = (const float*)d_in[8];
    const float* rm_b2  = (const float*)d_in[9];
    const float* mx_w1  = (const float*)d_in[10];
    const float* mx_b1  = (const float*)d_in[11];
    const float* mx_w2  = (const float*)d_in[12];
    const float* mx_b2  = (const float*)d_in[13];
    const float* my_w1  = (const float*)d_in[14];
    const float* my_b1  = (const float*)d_in[15];
    const float* my_w2  = (const float*)d_in[16];
    const float* my_b2  = (const float*)d_in[17];
    const float* ax_w1  = (const float*)d_in[18];
    const float* ax_b1  = (const float*)d_in[19];
    const float* ax_w2  = (const float*)d_in[20];
    const float* ax_b2  = (const float*)d_in[21];
    const float* ay_w1  = (const float*)d_in[22];
    const float* ay_b1  = (const float*)d_in[23];
    const float* ay_w2  = (const float*)d_in[24];
    const float* ay_b2  = (const float*)d_in[25];
    const float* mult_w = (const float*)d_in[26];
    const float* addx_w = (const float*)d_in[27];
    const float* addy_w = (const float*)d_in[28];
    const float* gbias  = (const float*)d_in[29];
    float* out = (float*)d_out;

    krb<<<24, 1024>>>(remb, rm_w1, rm_b1);
    k1a<<<dim3(8, 8), 512>>>(h_in, st_w1, st_b1);
    k1b<<<dim3(4, 16), 512>>>(st_w2, st_b2);
    k2a<<<dim3(4, 4, 24), 256>>>(rm_w1);
    k2b<<<dim3(4, 4, 24), 256>>>(rm_w2, rm_b2);
    k3a<<<dim3(4, 4, 48), 256>>>(mx_w1, mx_b1, my_w1, my_b1,
                                 ax_w1, ax_b1, ay_w1, ay_b1);
    k3b<<<dim3(48, 6), 256>>>(mx_w2, mx_b2, my_w2, my_b2,
                              ax_w2, ax_b2, ay_w2, ay_b2);
    k4<<<2176, 128>>>(mult_w, addx_w, addy_w, gbias);
    k5<<<dim3(16, 64), 128>>>(out);
}

// round 9
// speedup vs baseline: 1.5869x; 1.5869x over previous
#include <cuda_runtime.h>

// ---------------- problem constants ----------------
#define NB   64
#define DIN  768
#define HD   256
#define H2   512
#define NC   24
#define WOUT 512

// ---------------- scratch ----------------
__device__ float g_hid[NB * H2];
__device__ float g_shared_t[HD * NB];            // [c][b]
__device__ float g_rb[24 * HD];                  // rank bias: remb@W1bot + b1
__device__ float g_hdn[24 * HD * NB];            // [r][k][b]
__device__ float g_rf_t[24 * HD * NB];           // [r][h][b]
__device__ float g_hdn3[48 * HD * NB];           // [u][k][b]
__device__ float g_cp[4 * NB * 16 * NC];
__device__ float g_u[NB * 16 * WOUT];
__device__ float g_v[NB * 16 * WOUT];
__device__ float g_dx[NB * WOUT];
__device__ float g_dy[NB * WOUT];

// ---------------- helpers ----------------
typedef unsigned long long ull;

__device__ __forceinline__ ull pk2(float x, float y) {
    ull r; asm("mov.b64 %0, {%1,%2};" : "=l"(r) : "f"(x), "f"(y)); return r;
}
__device__ __forceinline__ void fma2(ull& d, ull a, ull b) {
    asm("fma.rn.f32x2 %0, %1, %2, %0;" : "+l"(d) : "l"(a), "l"(b));
}
__device__ __forceinline__ ull add2(ull a, ull b) {
    ull r; asm("add.rn.f32x2 %0, %1, %2;" : "=l"(r) : "l"(a), "l"(b)); return r;
}
__device__ __forceinline__ float2 up2(ull a) {
    float2 r; asm("mov.b64 {%0,%1}, %2;" : "=f"(r.x), "=f"(r.y) : "l"(a)); return r;
}
__device__ __forceinline__ float lk(float x) { return x >= 0.f ? x : 0.2f * x; }

__device__ __forceinline__ void cpa16(float* sdst, const float* gsrc) {
    unsigned sa = (unsigned)__cvta_generic_to_shared(sdst);
    asm volatile("cp.async.cg.shared.global [%0], [%1], 16;" :: "r"(sa), "l"(gsrc) : "memory");
}
#define CPA_COMMIT() asm volatile("cp.async.commit_group;" ::: "memory")

__device__ __forceinline__ void hcoef(int w, int& seg,
                                      float& h00, float& h10, float& h01, float& h11) {
    const float step = 0.998f / 511.f;
    float t  = 0.001f + (float)w * step;
    float ts = t * 23.f;
    int s = (int)floorf(ts);
    s = s < 0 ? 0 : (s > 22 ? 22 : s);
    float tau = ts - (float)s;
    tau = fminf(fmaxf(tau, 0.f), 0.9999f);
    float t2 = tau * tau, t3 = t2 * tau;
    h00 = 2.f * t3 - 3.f * t2 + 1.f;
    h10 = t3 - 2.f * t2 + tau;
    h01 = -2.f * t3 + 3.f * t2;
    h11 = t3 - t2;
    seg = s;
}
__device__ __forceinline__ float hermev(const float* cp, int s,
                                        float h00, float h10, float h01, float h11) {
    const float inv = 0.5f / 23.f;
    float pk  = cp[s];
    float pk1 = cp[s + 1];
    int jm = s - 1; if (jm < 0) jm = 0;
    float mk = (cp[s + 1] - cp[jm]) * inv;
    int j2 = s + 2; if (j2 > 23) j2 = 23;
    float mk1 = (cp[j2] - cp[s]) * inv;
    return h00 * pk + h10 * mk + h01 * pk1 + h11 * mk1;
}

// ======== GEMM body, 2-way K-split: 64 cols x 32 batch, K=256, 512 thr ========
// tid: ks = tid>>8 (K half), t = tid&255, quad = t&15 (4 cols), bg = t>>4 (2 batches).
// xs[256][32]: activations [k][b] (32 batches). ws: per-half 2-stage weight buffer
// (2 halves x 2 stages x 16 rows x 64 cols = 16 KB); exchange overlays ws at end.
// wsrc: gmem weights, row stride HD, pre-offset to block's 64-col slice.
// On exit, ks==0 threads hold the full-K acc[4] (col-pair x 2 batches).
__device__ __forceinline__ void gemm_ks(const float* __restrict__ wsrc_full,
                                        const float* xs, float* ws,
                                        ull* acc, int tid) {
    int ks = tid >> 8, t = tid & 255;
    int quad = t & 15, bg = t >> 4;
    int row = t >> 4, seg = t & 15;          // staging role
    const float* wsrc = wsrc_full + ks * 128 * HD;
    float* wbase = ws + ks * 2048;           // 2 stages x 1024 floats

    // prologue: stage chunk 0
    cpa16(wbase + row * 64 + seg * 4, wsrc + row * HD + seg * 4);
    CPA_COMMIT();

    #pragma unroll 1
    for (int c = 0; c < 8; c++) {
        if (c < 7) {
            const float* gs = wsrc + (c + 1) * 16 * HD;
            float* wdst = wbase + ((c + 1) & 1) * 1024;
            cpa16(wdst + row * 64 + seg * 4, gs + row * HD + seg * 4);
            CPA_COMMIT();
            asm volatile("cp.async.wait_group 1;" ::: "memory");
        } else {
            asm volatile("cp.async.wait_group 0;" ::: "memory");
        }
        __syncthreads();
        const float* wst = wbase + (c & 1) * 1024;
        const float* xc  = xs + (ks * 128 + c * 16) * 32;
        #pragma unroll
        for (int kk = 0; kk < 16; kk++) {
            ulonglong2 wp = *(const ulonglong2*)(wst + kk * 64 + quad * 4);
            float2 xv = *(const float2*)(xc + kk * 32 + bg * 2);
            ull x0 = pk2(xv.x, xv.x), x1 = pk2(xv.y, xv.y);
            fma2(acc[0], wp.x, x0); fma2(acc[1], wp.x, x1);
            fma2(acc[2], wp.y, x0); fma2(acc[3], wp.y, x1);
        }
        __syncthreads();
    }

    // combine halves through smem (overlay on ws; 8 KB used)
    ull* ex = (ull*)ws;
    if (ks == 1) {
        #pragma unroll
        for (int j = 0; j < 4; j++) ex[t * 4 + j] = acc[j];
    }
    __syncthreads();
    if (ks == 0) {
        #pragma unroll
        for (int j = 0; j < 4; j++) acc[j] = add2(acc[j], ex[t * 4 + j]);
    }
}

// stage x[256][32] from a global [256][NB] slab at batch offset b0 (32 batches), 512 thr
__device__ __forceinline__ void stage_x(float* xs, const float* __restrict__ src,
                                        int b0, int tid) {
    #pragma unroll
    for (int s = tid; s < 2048; s += 512) {
        int d = s >> 3, seg = s & 7;
        *(ulonglong2*)(xs + d * 32 + seg * 4) =
            *(const ulonglong2*)(src + d * NB + b0 + seg * 4);
    }
}

// ---------------- K1a ----------------
__global__ void __launch_bounds__(512) k1a(const float* __restrict__ hin,
                                           const float* __restrict__ w1,
                                           const float* __restrict__ b1) {
    __shared__ __align__(16) float sm[DIN * 12];
    int tid = threadIdx.x;
    int c = tid & 63, ks = tid >> 6;
    int hc = blockIdx.x, btile = blockIdx.y;
    int b0 = btile * 8;
    int hcol = hc * 64 + c;

    for (int i = tid; i < 8 * DIN; i += 512) {
        int bb = i / DIN, d = i - bb * DIN;
        sm[d * 12 + bb] = hin[(b0 + bb) * DIN + d];
    }
    __syncthreads();

    ull acc[4];
#pragma unroll
    for (int j = 0; j < 4; j++) acc[j] = 0ull;
    const float* w1p = w1 + hcol;
    int d0 = ks * 96;
#pragma unroll 4
    for (int dd = 0; dd < 96; dd++) {
        int d = d0 + dd;
        float w = w1p[d * H2];
        ull wp = pk2(w, w);
        const ulonglong2* xr = (const ulonglong2*)(sm + d * 12);
        ulonglong2 p0 = xr[0], p1 = xr[1];
        fma2(acc[0], wp, p0.x); fma2(acc[1], wp, p0.y);
        fma2(acc[2], wp, p1.x); fma2(acc[3], wp, p1.y);
    }
    __syncthreads();
    ull* part = (ull*)sm;
#pragma unroll
    for (int j = 0; j < 4; j++) part[tid * 4 + j] = acc[j];
    __syncthreads();
    if (tid < 256) {
        int cc = tid & 63, j = tid >> 6;
        ull s = part[cc * 4 + j];
#pragma unroll
        for (int k = 1; k < 8; k++) s = add2(s, part[(k * 64 + cc) * 4 + j]);
        int hco = hc * 64 + cc;
        float2 p = up2(s);
        float bias = b1[hco];
        g_hid[(b0 + 2 * j) * H2 + hco]     = lk(p.x + bias);
        g_hid[(b0 + 2 * j + 1) * H2 + hco] = lk(p.y + bias);
    }
}

// ---------------- K1b ----------------
__global__ void __launch_bounds__(512) k1b(const float* __restrict__ w2,
                                           const float* __restrict__ b2) {
    __shared__ __align__(16) float sm[H2 * 8];
    int tid = threadIdx.x;
    int c = tid & 63, ks = tid >> 6;
    int cc = blockIdx.x, btile = blockIdx.y;
    int b0 = btile * 4;
    int ccol = cc * 64 + c;

    for (int i = tid; i < 4 * H2; i += 512) {
        int bb = i >> 9, d = i & 511;
        sm[d * 8 + bb] = g_hid[(b0 + bb) * H2 + d];
    }
    __syncthreads();

    ull acc[2] = {0ull, 0ull};
    const float* wp2 = w2 + ccol;
    int d0 = ks * 64;
#pragma unroll 4
    for (int dd = 0; dd < 64; dd++) {
        int d = d0 + dd;
        float w = wp2[d * HD];
        ull wp = pk2(w, w);
        ulonglong2 p0 = *(const ulonglong2*)(sm + d * 8);
        fma2(acc[0], wp, p0.x); fma2(acc[1], wp, p0.y);
    }
    __syncthreads();
    ull* part = (ull*)sm;
    part[tid * 2 + 0] = acc[0];
    part[tid * 2 + 1] = acc[1];
    __syncthreads();
    if (tid < 128) {
        int c2 = tid & 63, j = tid >> 6;
        ull s = part[c2 * 2 + j];
#pragma unroll
        for (int k = 1; k < 8; k++) s = add2(s, part[(k * 64 + c2) * 2 + j]);
        int co = cc * 64 + c2;
        float2 p = up2(s);
        float bias = b2[co];
        g_shared_t[co * NB + b0 + 2 * j]     = p.x + bias;
        g_shared_t[co * NB + b0 + 2 * j + 1] = p.y + bias;
    }
}

// ---------------- KRB ----------------
__global__ void __launch_bounds__(1024) krb(const float* __restrict__ remb,
                                            const float* __restrict__ w1,
                                            const float* __restrict__ b1) {
    __shared__ float part[1024];
    int tid = threadIdx.x;
    int col = tid & 255, ks = tid >> 8;
    int r = blockIdx.x;
    const float* wp = w1 + (r * H2 + HD + ks * 64) * HD + col;
    const float* rp = remb + r * HD + ks * 64;
    float a = 0.f;
#pragma unroll 8
    for (int d = 0; d < 64; d++)
        a = fmaf(__ldg(rp + d), wp[d * HD], a);
    part[tid] = a;
    __syncthreads();
    if (ks == 0) {
        a += part[256 + col] + part[512 + col] + part[768 + col];
        g_rb[r * HD + col] = a + b1[r * HD + col];
    }
}

// ---------------- K2a: hdn = leaky(shared @ W1_top + rb) ----------------
// grid (4 ch, 2 bh, 24 r), block 512
__global__ void __launch_bounds__(512) k2a(const float* __restrict__ w1) {
    __shared__ __align__(16) float xs[HD * 32];   // 32 KB
    __shared__ __align__(16) float ws[4 * 1024];  // 16 KB
    int tid = threadIdx.x;
    int ch = blockIdx.x, bh = blockIdx.y, r = blockIdx.z;
    int b0 = bh * 32;
    const float* wsrc = w1 + (size_t)r * H2 * HD + ch * 64;

    stage_x(xs, g_shared_t, b0, tid);

    ull acc[4] = {0ull, 0ull, 0ull, 0ull};
    gemm_ks(wsrc, xs, ws, acc, tid);

    if (tid < 256) {
        int quad = tid & 15, bg = tid >> 4;
        int col0 = ch * 64 + quad * 4;
        float2 rb01 = *(const float2*)(g_rb + r * HD + col0);
        float2 rb23 = *(const float2*)(g_rb + r * HD + col0 + 2);
        float2 a00 = up2(acc[0]), a01 = up2(acc[1]);   // (c0,c1)@b0, (c0,c1)@b1
        float2 a10 = up2(acc[2]), a11 = up2(acc[3]);   // (c2,c3)@b0, (c2,c3)@b1
        float* base = g_hdn + (size_t)(r * HD + col0) * NB + b0 + bg * 2;
        *(float2*)(base + 0 * NB) = make_float2(lk(a00.x + rb01.x), lk(a01.x + rb01.x));
        *(float2*)(base + 1 * NB) = make_float2(lk(a00.y + rb01.y), lk(a01.y + rb01.y));
        *(float2*)(base + 2 * NB) = make_float2(lk(a10.x + rb23.x), lk(a11.x + rb23.x));
        *(float2*)(base + 3 * NB) = make_float2(lk(a10.y + rb23.y), lk(a11.y + rb23.y));
    }
}

// ---------------- K2b: rf = hdn @ W2 + b2 ----------------
__global__ void __launch_bounds__(512) k2b(const float* __restrict__ w2,
                                           const float* __restrict__ b2) {
    __shared__ __align__(16) float xs[HD * 32];
    __shared__ __align__(16) float ws[4 * 1024];
    int tid = threadIdx.x;
    int ch = blockIdx.x, bh = blockIdx.y, r = blockIdx.z;
    int b0 = bh * 32;
    const float* wsrc = w2 + (size_t)r * HD * HD + ch * 64;

    stage_x(xs, g_hdn + (size_t)r * HD * NB, b0, tid);

    ull acc[4] = {0ull, 0ull, 0ull, 0ull};
    gemm_ks(wsrc, xs, ws, acc, tid);

    if (tid < 256) {
        int quad = tid & 15, bg = tid >> 4;
        int col0 = ch * 64 + quad * 4;
        float2 bi01 = *(const float2*)(b2 + r * HD + col0);
        float2 bi23 = *(const float2*)(b2 + r * HD + col0 + 2);
        float2 a00 = up2(acc[0]), a01 = up2(acc[1]);
        float2 a10 = up2(acc[2]), a11 = up2(acc[3]);
        float* base = g_rf_t + (size_t)(r * HD + col0) * NB + b0 + bg * 2;
        *(float2*)(base + 0 * NB) = make_float2(a00.x + bi01.x, a01.x + bi01.x);
        *(float2*)(base + 1 * NB) = make_float2(a00.y + bi01.y, a01.y + bi01.y);
        *(float2*)(base + 2 * NB) = make_float2(a10.x + bi23.x, a11.x + bi23.x);
        *(float2*)(base + 3 * NB) = make_float2(a10.y + bi23.y, a11.y + bi23.y);
    }
}

// ---------------- K3a: cp-gen layer1, 48 units ----------------
// grid (4 ch, 2 bh, 48 u), block 512
__global__ void __launch_bounds__(512) k3a(
        const float* __restrict__ mxw1, const float* __restrict__ mxb1,
        const float* __restrict__ myw1, const float* __restrict__ myb1,
        const float* __restrict__ axw1, const float* __restrict__ axb1,
        const float* __restrict__ ayw1, const float* __restrict__ ayb1) {
    __shared__ __align__(16) float xs[HD * 32];
    __shared__ __align__(16) float ws[4 * 1024];
    int tid = threadIdx.x;
    int ch = blockIdx.x, bh = blockIdx.y, u = blockIdx.z;
    int b0 = bh * 32;

    const float *w1, *b1;
    int r, src_r;
    if (u < 16)      { r = u;      src_r = u;      w1 = mxw1; b1 = mxb1; }
    else if (u < 32) { r = u - 16; src_r = r;      w1 = myw1; b1 = myb1; }
    else if (u < 40) { r = u - 32; src_r = 16 + r; w1 = axw1; b1 = axb1; }
    else             { r = u - 40; src_r = 16 + r; w1 = ayw1; b1 = ayb1; }
    const float* wsrc = w1 + (size_t)r * HD * HD + ch * 64;

    stage_x(xs, g_rf_t + (size_t)src_r * HD * NB, b0, tid);

    ull acc[4] = {0ull, 0ull, 0ull, 0ull};
    gemm_ks(wsrc, xs, ws, acc, tid);

    if (tid < 256) {
        int quad = tid & 15, bg = tid >> 4;
        int col0 = ch * 64 + quad * 4;
        float2 bi01 = *(const float2*)(b1 + r * HD + col0);
        float2 bi23 = *(const float2*)(b1 + r * HD + col0 + 2);
        float2 a00 = up2(acc[0]), a01 = up2(acc[1]);
        float2 a10 = up2(acc[2]), a11 = up2(acc[3]);
        float* base = g_hdn3 + (size_t)(u * HD + col0) * NB + b0 + bg * 2;
        *(float2*)(base + 0 * NB) = make_float2(lk(a00.x + bi01.x), lk(a01.x + bi01.x));
        *(float2*)(base + 1 * NB) = make_float2(lk(a00.y + bi01.y), lk(a01.y + bi01.y));
        *(float2*)(base + 2 * NB) = make_float2(lk(a10.x + bi23.x), lk(a11.x + bi23.x));
        *(float2*)(base + 3 * NB) = make_float2(lk(a10.y + bi23.y), lk(a11.y + bi23.y));
    }
}

// ---------------- K3b ----------------
__global__ void __launch_bounds__(256) k3b(
        const float* __restrict__ mxw2, const float* __restrict__ mxb2,
        const float* __restrict__ myw2, const float* __restrict__ myb2,
        const float* __restrict__ axw2, const float* __restrict__ axb2,
        const float* __restrict__ ayw2, const float* __restrict__ ayb2) {
    __shared__ __align__(16) float wcol[HD * 4];
    int tid = threadIdx.x;
    int b = tid & 63, ci = tid >> 6;
    int u = blockIdx.x, cg = blockIdx.y;
    int c = cg * 4 + ci;

    const float *w2, *b2;
    int r, gen;
    if (u < 16)      { r = u;      gen = 0; w2 = mxw2; b2 = mxb2; }
    else if (u < 32) { r = u - 16; gen = 1; w2 = myw2; b2 = myb2; }
    else if (u < 40) { r = u - 32; gen = 2; w2 = axw2; b2 = axb2; }
    else             { r = u - 40; gen = 3; w2 = ayw2; b2 = ayb2; }
    w2 += r * HD * NC; b2 += r * NC;

    for (int i = tid; i < HD * 4; i += 256) {
        int k = i >> 2, cc = i & 3;
        wcol[i] = w2[k * NC + cg * 4 + cc];
    }
    __syncthreads();

    const float* hp = g_hdn3 + (size_t)(u * HD) * NB + b;
    float a0 = 0.f, a1 = 0.f, a2 = 0.f, a3 = 0.f;
#pragma unroll 8
    for (int k = 0; k < HD; k += 4) {
        a0 = fmaf(wcol[(k + 0) * 4 + ci], hp[(k + 0) * NB], a0);
        a1 = fmaf(wcol[(k + 1) * 4 + ci], hp[(k + 1) * NB], a1);
        a2 = fmaf(wcol[(k + 2) * 4 + ci], hp[(k + 2) * NB], a2);
        a3 = fmaf(wcol[(k + 3) * 4 + ci], hp[(k + 3) * NB], a3);
    }
    float a = (a0 + a1) + (a2 + a3) + b2[c];
    g_cp[((gen * NB + b) * 16 + r) * NC + c] = a;
}

// ---------------- K4 ----------------
__global__ void __launch_bounds__(128) k4(const float* __restrict__ mw,
                                          const float* __restrict__ axw,
                                          const float* __restrict__ ayw,
                                          const float* __restrict__ gb) {
    __shared__ __align__(16) float cps[8][24];
    __shared__ float wg[16];
    int tid = threadIdx.x, x = blockIdx.x;

    if (x < 2048) {
        int isv = x >> 10;
        int xx = x & 1023;
        int b = xx >> 4, r = xx & 15;
        const float* cp = g_cp + ((isv * NB + b) * 16 + r) * NC;
        if (tid < NC) cps[0][tid] = cp[tid];
        if (tid == 0) {
            if (isv) {
                float mx = mw[0];
                for (int i = 1; i < 16; i++) mx = fmaxf(mx, mw[i]);
                float s = 0.f, er = 0.f;
                for (int i = 0; i < 16; i++) { float e = expf(mw[i] - mx); s += e; if (i == r) er = e; }
                wg[0] = er / s;
            } else wg[0] = 1.f;
        }
        __syncthreads();
        float sc = wg[0];
        float o[4];
#pragma unroll
        for (int i = 0; i < 4; i++) {
            int w = tid * 4 + i;
            int seg; float h00, h10, h01, h11;
            hcoef(w, seg, h00, h10, h01, h11);
            o[i] = sc * hermev(cps[0], seg, h00, h10, h01, h11);
        }
        float* op = (isv ? g_v : g_u) + (b * 16 + r) * WOUT + tid * 4;
        *(float4*)op = make_float4(o[0], o[1], o[2], o[3]);
    } else {
        int isy = (x >= 2112);
        int b = x - (isy ? 2112 : 2048);
        int gen = 2 + isy;
        for (int i = tid; i < 8 * NC; i += 128) {
            int rr = i / NC, c = i - rr * NC;
            cps[rr][c] = g_cp[((gen * NB + b) * 16 + rr) * NC + c];
        }
        if (tid == 0) {
            const float* ww = isy ? ayw : axw;
            float mx = ww[0];
            for (int i = 1; i < 8; i++) mx = fmaxf(mx, ww[i]);
            float s = 0.f, e[8];
            for (int i = 0; i < 8; i++) { e[i] = expf(ww[i] - mx); s += e[i]; }
            for (int i = 0; i < 8; i++) wg[i] = e[i] / s;
        }
        __syncthreads();
        float base = isy ? gb[0] : 0.f;
        float o[4];
#pragma unroll
        for (int i = 0; i < 4; i++) {
            int w = tid * 4 + i;
            int seg; float h00, h10, h01, h11;
            hcoef(w, seg, h00, h10, h01, h11);
            float a = base;
#pragma unroll
            for (int rr = 0; rr < 8; rr++)
                a = fmaf(wg[rr], hermev(cps[rr], seg, h00, h10, h01, h11), a);
            o[i] = a;
        }
        float* op = (isy ? g_dy : g_dx) + b * WOUT + tid * 4;
        *(float4*)op = make_float4(o[0], o[1], o[2], o[3]);
    }
}

// ---------------- K5 ----------------
__global__ void __launch_bounds__(128) k5(float* __restrict__ out) {
    __shared__ __align__(16) float wv[32][36];
    __shared__ float dys[32];
    int tid = threadIdx.x;
    int ht = blockIdx.x, b = blockIdx.y;
    int h0 = ht * 32;

    for (int i = tid; i < 512; i += 128) {
        int r = i >> 5, hh = i & 31;
        float v = g_v[(b * 16 + r) * WOUT + h0 + hh];
        wv[hh][2 * r] = v;
        wv[hh][2 * r + 1] = v;
    }
    if (tid < 32) dys[tid] = g_dy[b * WOUT + h0 + tid];

    int w = tid * 4;
    ull ur2[32];
#pragma unroll
    for (int r = 0; r < 16; r++) {
        float4 t = *(const float4*)(g_u + (b * 16 + r) * WOUT + w);
        ur2[2 * r]     = pk2(t.x, t.y);
        ur2[2 * r + 1] = pk2(t.z, t.w);
    }
    float4 dx4 = *(const float4*)(g_dx + b * WOUT + w);
    ull dxp0 = pk2(dx4.x, dx4.y), dxp1 = pk2(dx4.z, dx4.w);
    __syncthreads();

    float* op = out + (size_t)b * (512 * 512) + (size_t)h0 * 512 + w;
#pragma unroll 2
    for (int hh = 0; hh < 32; hh++) {
        float dyv = dys[hh];
        ull dyp = pk2(dyv, dyv);
        ull a0 = add2(dxp0, dyp);
        ull a1 = add2(dxp1, dyp);
        const ulonglong2* row = (const ulonglong2*)&wv[hh][0];
#pragma unroll
        for (int i = 0; i < 8; i++) {
            ulonglong2 c = row[i];
            fma2(a0, c.x, ur2[4 * i]);
            fma2(a1, c.x, ur2[4 * i + 1]);
            fma2(a0, c.y, ur2[4 * i + 2]);
            fma2(a1, c.y, ur2[4 * i + 3]);
        }
        float2 lo = up2(a0), hi = up2(a1);
        *(float4*)(op + hh * 512) = make_float4(lo.x, lo.y, hi.x, hi.y);
    }
}

// ---------------- launch ----------------
extern "C" void kernel_launch(void* const* d_in, const int* in_sizes, int n_in,
                              void* d_out, int out_size) {
    const float* h_in   = (const float*)d_in[0];
    const float* remb   = (const float*)d_in[1];
    const float* st_w1  = (const float*)d_in[2];
    const float* st_b1  = (const float*)d_in[3];
    const float* st_w2  = (const float*)d_in[4];
    const float* st_b2  = (const float*)d_in[5];
    const float* rm_w1  = (const float*)d_in[6];
    const float* rm_b1  = (const float*)d_in[7];
    const float* rm_w2  = (const float*)d_in[8];
    const float* rm_b2  = (const float*)d_in[9];
    const float* mx_w1  = (const float*)d_in[10];
    const float* mx_b1  = (const float*)d_in[11];
    const float* mx_w2  = (const float*)d_in[12];
    const float* mx_b2  = (const float*)d_in[13];
    const float* my_w1  = (const float*)d_in[14];
    const float* my_b1  = (const float*)d_in[15];
    const float* my_w2  = (const float*)d_in[16];
    const float* my_b2  = (const float*)d_in[17];
    const float* ax_w1  = (const float*)d_in[18];
    const float* ax_b1  = (const float*)d_in[19];
    const float* ax_w2  = (const float*)d_in[20];
    const float* ax_b2  = (const float*)d_in[21];
    const float* ay_w1  = (const float*)d_in[22];
    const float* ay_b1  = (const float*)d_in[23];
    const float* ay_w2  = (const float*)d_in[24];
    const float* ay_b2  = (const float*)d_in[25];
    const float* mult_w = (const float*)d_in[26];
    const float* addx_w = (const float*)d_in[27];
    const float* addy_w = (const float*)d_in[28];
    const float* gbias  = (const float*)d_in[29];
    float* out = (float*)d_out;

    krb<<<24, 1024>>>(remb, rm_w1, rm_b1);
    k1a<<<dim3(8, 8), 512>>>(h_in, st_w1, st_b1);
    k1b<<<dim3(4, 16), 512>>>(st_w2, st_b2);
    k2a<<<dim3(4, 2, 24), 512>>>(rm_w1);
    k2b<<<dim3(4, 2, 24), 512>>>(rm_w2, rm_b2);
    k3a<<<dim3(4, 2, 48), 512>>>(mx_w1, mx_b1, my_w1, my_b1,
                                 ax_w1, ax_b1, ay_w1, ay_b1);
    k3b<<<dim3(48, 6), 256>>>(mx_w2, mx_b2, my_w2, my_b2,
                              ax_w2, ax_b2, ay_w2, ay_b2);
    k4<<<2176, 128>>>(mult_w, addx_w, addy_w, gbias);
    k5<<<dim3(16, 64), 128>>>(out);
}